// round 1
// baseline (speedup 1.0000x reference)
#include <cuda_runtime.h>

// ---------------------------------------------------------------------------
// Problem constants
// ---------------------------------------------------------------------------
#define TT   2048      // B*S total rows
#define DIM  7168
#define NH   64        // heads
#define HD   128       // head dim
#define RD   64        // rope dims
#define QL   1536
#define HHD  8192      // NH*HD
#define SQ   1024      // sequence (per batch)
#define EPSV 1e-6f
#define SCALEV 0.08838834764831845f   // 128^-0.5

// ---------------------------------------------------------------------------
// Scratch (device globals: allocation-free, graph-capture safe)
// ---------------------------------------------------------------------------
__device__ float g_q[TT * HHD];    // 64 MB : q = qr @ Wq (then roped in place)
__device__ float g_kp[TT * HD];    // pre-LN k projection
__device__ float g_k[TT * HD];     // final k (LN + rope)
__device__ float g_w[TT * NH];     // per-head weights

// ---------------------------------------------------------------------------
// SGEMM  BM=128, BN=64, BK=16, 256 threads, 8x4 per-thread tile
// C[M,N] = A[M,K] @ B[K,N], all row-major fp32. M%128==0, N%64==0, K%16==0.
// ---------------------------------------------------------------------------
__global__ __launch_bounds__(256) void sgemm128(const float* __restrict__ A,
                                                const float* __restrict__ B,
                                                float* __restrict__ C,
                                                int M, int N, int K) {
    __shared__ float As[16][128 + 4];   // [k][m], padded
    __shared__ float Bs[16][64];        // [k][n]

    const int tid = threadIdx.x;
    const int m0  = blockIdx.y * 128;
    const int n0  = blockIdx.x * 64;
    const int ty  = tid >> 4;   // 0..15 (M groups of 8)
    const int tx  = tid & 15;   // 0..15 (N groups of 4)

    float acc[8][4];
#pragma unroll
    for (int i = 0; i < 8; i++)
#pragma unroll
        for (int j = 0; j < 4; j++) acc[i][j] = 0.f;

    for (int kt = 0; kt < K; kt += 16) {
        // load A tile 128x16 (2 float4 per thread), store transposed
#pragma unroll
        for (int r = 0; r < 2; r++) {
            int lin = r * 256 + tid;
            int row = lin >> 2, c4 = lin & 3;
            float4 v = *(const float4*)(A + (size_t)(m0 + row) * K + kt + c4 * 4);
            As[c4 * 4 + 0][row] = v.x;
            As[c4 * 4 + 1][row] = v.y;
            As[c4 * 4 + 2][row] = v.z;
            As[c4 * 4 + 3][row] = v.w;
        }
        // load B tile 16x64 (1 float4 per thread)
        {
            int row = tid >> 4, c4 = tid & 15;
            float4 v = *(const float4*)(B + (size_t)(kt + row) * N + n0 + c4 * 4);
            *(float4*)&Bs[row][c4 * 4] = v;
        }
        __syncthreads();

#pragma unroll
        for (int kk = 0; kk < 16; kk++) {
            float4 a0 = *(const float4*)&As[kk][ty * 8];
            float4 a1 = *(const float4*)&As[kk][ty * 8 + 4];
            float4 b0 = *(const float4*)&Bs[kk][tx * 4];
            float a[8] = {a0.x, a0.y, a0.z, a0.w, a1.x, a1.y, a1.z, a1.w};
            float b[4] = {b0.x, b0.y, b0.z, b0.w};
#pragma unroll
            for (int i = 0; i < 8; i++)
#pragma unroll
                for (int j = 0; j < 4; j++) acc[i][j] = fmaf(a[i], b[j], acc[i][j]);
        }
        __syncthreads();
    }

#pragma unroll
    for (int i = 0; i < 8; i++) {
        float4 v = make_float4(acc[i][0], acc[i][1], acc[i][2], acc[i][3]);
        *(float4*)(C + (size_t)(m0 + ty * 8 + i) * N + n0 + tx * 4) = v;
    }
}

// ---------------------------------------------------------------------------
// SGEMM  BM=32, BN=64 (more blocks for the skinny k/w projections)
// ---------------------------------------------------------------------------
__global__ __launch_bounds__(256) void sgemm32(const float* __restrict__ A,
                                               const float* __restrict__ B,
                                               float* __restrict__ C,
                                               int M, int N, int K) {
    __shared__ float As[16][32 + 4];
    __shared__ float Bs[16][64];

    const int tid = threadIdx.x;
    const int m0  = blockIdx.y * 32;
    const int n0  = blockIdx.x * 64;
    const int ty  = tid >> 4;   // 0..15 (M groups of 2)
    const int tx  = tid & 15;   // 0..15 (N groups of 4)

    float acc[2][4];
#pragma unroll
    for (int i = 0; i < 2; i++)
#pragma unroll
        for (int j = 0; j < 4; j++) acc[i][j] = 0.f;

    for (int kt = 0; kt < K; kt += 16) {
        if (tid < 128) {                       // A tile 32x16 = 128 float4
            int row = tid >> 2, c4 = tid & 3;
            float4 v = *(const float4*)(A + (size_t)(m0 + row) * K + kt + c4 * 4);
            As[c4 * 4 + 0][row] = v.x;
            As[c4 * 4 + 1][row] = v.y;
            As[c4 * 4 + 2][row] = v.z;
            As[c4 * 4 + 3][row] = v.w;
        }
        {
            int row = tid >> 4, c4 = tid & 15;
            float4 v = *(const float4*)(B + (size_t)(kt + row) * N + n0 + c4 * 4);
            *(float4*)&Bs[row][c4 * 4] = v;
        }
        __syncthreads();

#pragma unroll
        for (int kk = 0; kk < 16; kk++) {
            float2 a0 = *(const float2*)&As[kk][ty * 2];
            float4 b0 = *(const float4*)&Bs[kk][tx * 4];
            float a[2] = {a0.x, a0.y};
            float b[4] = {b0.x, b0.y, b0.z, b0.w};
#pragma unroll
            for (int i = 0; i < 2; i++)
#pragma unroll
                for (int j = 0; j < 4; j++) acc[i][j] = fmaf(a[i], b[j], acc[i][j]);
        }
        __syncthreads();
    }

#pragma unroll
    for (int i = 0; i < 2; i++) {
        float4 v = make_float4(acc[i][0], acc[i][1], acc[i][2], acc[i][3]);
        *(float4*)(C + (size_t)(m0 + ty * 2 + i) * N + n0 + tx * 4) = v;
    }
}

// ---------------------------------------------------------------------------
// In-place interleaved RoPE on q (first RD dims of each head).
// One block per token row t; 2048 pairs (64 heads x 32 pairs).
// ---------------------------------------------------------------------------
__global__ __launch_bounds__(256) void rope_q(float* __restrict__ q,
                                              const float* __restrict__ cosv,
                                              const float* __restrict__ sinv) {
    const int t = blockIdx.x;
    const float* ct = cosv + t * RD;
    const float* st = sinv + t * RD;
    float* qt = q + (size_t)t * HHD;
#pragma unroll
    for (int it = 0; it < 8; it++) {
        int p = it * 256 + threadIdx.x;   // 0..2047
        int h = p >> 5;
        int i = p & 31;
        float c = ct[2 * i];
        float s = st[2 * i];
        float2* addr = (float2*)(qt + h * HD + 2 * i);
        float2 v = *addr;
        *addr = make_float2(v.x * c - v.y * s, v.y * c + v.x * s);
    }
}

// ---------------------------------------------------------------------------
// LayerNorm(kp) * gamma + beta, then interleaved RoPE on first RD dims -> g_k
// One block (128 threads) per token row.
// ---------------------------------------------------------------------------
__global__ __launch_bounds__(128) void ln_rope_k(const float* __restrict__ kp,
                                                 const float* __restrict__ cosv,
                                                 const float* __restrict__ sinv,
                                                 const float* __restrict__ gamma,
                                                 const float* __restrict__ beta,
                                                 float* __restrict__ kout) {
    const int t = blockIdx.x;
    const int d = threadIdx.x;
    float v = kp[t * HD + d];
    float s1 = v, s2 = v * v;
#pragma unroll
    for (int off = 16; off; off >>= 1) {
        s1 += __shfl_xor_sync(0xffffffffu, s1, off);
        s2 += __shfl_xor_sync(0xffffffffu, s2, off);
    }
    __shared__ float r1[4], r2[4];
    if ((d & 31) == 0) { r1[d >> 5] = s1; r2[d >> 5] = s2; }
    __syncthreads();
    float sum = r1[0] + r1[1] + r1[2] + r1[3];
    float sq  = r2[0] + r2[1] + r2[2] + r2[3];
    float mu  = sum * (1.f / HD);
    float var = sq * (1.f / HD) - mu * mu;
    float kn  = (v - mu) * rsqrtf(var + EPSV) * gamma[d] + beta[d];

    __shared__ float ks[HD];
    ks[d] = kn;
    __syncthreads();
    float out = kn;
    if (d < RD) {
        float c = cosv[t * RD + (d & ~1)];
        float s = sinv[t * RD + (d & ~1)];
        float partner = ks[d ^ 1];
        out = ((d & 1) == 0) ? (kn * c - partner * s)
                             : (kn * c + partner * s);
    }
    kout[t * HD + d] = out;
}

// ---------------------------------------------------------------------------
// scores[b,i,k] = scale * sum_h w[b,i,h] * relu( q[b,i,h,:] . k[b,k,:] )
// Block = one (t = b*1024+i) x one 128-wide k tile. 64x128x128 GEMM + reduce.
// ---------------------------------------------------------------------------
#define SKT 128
__global__ __launch_bounds__(256) void scores_kernel(const float* __restrict__ q,
                                                     const float* __restrict__ k,
                                                     const float* __restrict__ w,
                                                     float* __restrict__ out) {
    const int t  = blockIdx.y;           // 0..2047
    const int k0 = blockIdx.x * SKT;     // k tile start within batch
    const int b  = t >> 10;

    __shared__ float Qs[32][64 + 4];     // [d][h]
    __shared__ float Ks[32][SKT + 4];    // [d][k]
    __shared__ float ws[NH];
    __shared__ float red[16][SKT];

    const int tid = threadIdx.x;
    const int ty  = tid >> 4;   // 0..15, 4 heads each
    const int tx  = tid & 15;   // 0..15, 8 k's each

    if (tid < NH) ws[tid] = w[t * NH + tid] * SCALEV;

    float acc[4][8];
#pragma unroll
    for (int i = 0; i < 4; i++)
#pragma unroll
        for (int j = 0; j < 8; j++) acc[i][j] = 0.f;

    const float* qrow = q + (size_t)t * HHD;
    const float* kbase = k + (size_t)(b * SQ + k0) * HD;

    for (int d0 = 0; d0 < HD; d0 += 32) {
        // Q tile: 64 h x 32 d  (512 float4, 2 per thread), transposed
#pragma unroll
        for (int r = 0; r < 2; r++) {
            int lin = r * 256 + tid;           // 0..511
            int h = lin >> 3, c4 = lin & 7;
            float4 v = *(const float4*)(qrow + h * HD + d0 + c4 * 4);
            Qs[c4 * 4 + 0][h] = v.x;
            Qs[c4 * 4 + 1][h] = v.y;
            Qs[c4 * 4 + 2][h] = v.z;
            Qs[c4 * 4 + 3][h] = v.w;
        }
        // K tile: 128 k x 32 d (1024 float4, 4 per thread), transposed
#pragma unroll
        for (int r = 0; r < 4; r++) {
            int lin = r * 256 + tid;           // 0..1023
            int kr = lin >> 3, c4 = lin & 7;
            float4 v = *(const float4*)(kbase + kr * HD + d0 + c4 * 4);
            Ks[c4 * 4 + 0][kr] = v.x;
            Ks[c4 * 4 + 1][kr] = v.y;
            Ks[c4 * 4 + 2][kr] = v.z;
            Ks[c4 * 4 + 3][kr] = v.w;
        }
        __syncthreads();

#pragma unroll
        for (int dd = 0; dd < 32; dd++) {
            float4 a0 = *(const float4*)&Qs[dd][ty * 4];
            float4 b0 = *(const float4*)&Ks[dd][tx * 8];
            float4 b1 = *(const float4*)&Ks[dd][tx * 8 + 4];
            float a[4] = {a0.x, a0.y, a0.z, a0.w};
            float bb[8] = {b0.x, b0.y, b0.z, b0.w, b1.x, b1.y, b1.z, b1.w};
#pragma unroll
            for (int i = 0; i < 4; i++)
#pragma unroll
                for (int j = 0; j < 8; j++) acc[i][j] = fmaf(a[i], bb[j], acc[i][j]);
        }
        __syncthreads();
    }

    // weighted relu partial over this thread's 4 heads
    float part[8];
#pragma unroll
    for (int j = 0; j < 8; j++) part[j] = 0.f;
#pragma unroll
    for (int i = 0; i < 4; i++) {
        float wh = ws[ty * 4 + i];
#pragma unroll
        for (int j = 0; j < 8; j++) part[j] += wh * fmaxf(acc[i][j], 0.f);
    }
#pragma unroll
    for (int j = 0; j < 8; j++) red[ty][tx * 8 + j] = part[j];
    __syncthreads();

#pragma unroll
    for (int off = 8; off; off >>= 1) {
        if (ty < off) {
#pragma unroll
            for (int j = 0; j < 8; j++)
                red[ty][tx * 8 + j] += red[ty + off][tx * 8 + j];
        }
        __syncthreads();
    }

    if (ty == 0) {
        float4 v0 = make_float4(red[0][tx * 8 + 0], red[0][tx * 8 + 1],
                                red[0][tx * 8 + 2], red[0][tx * 8 + 3]);
        float4 v1 = make_float4(red[0][tx * 8 + 4], red[0][tx * 8 + 5],
                                red[0][tx * 8 + 6], red[0][tx * 8 + 7]);
        float* o = out + (size_t)t * SQ + k0 + tx * 8;
        *(float4*)o = v0;
        *(float4*)(o + 4) = v1;
    }
}

// ---------------------------------------------------------------------------
// launch
// ---------------------------------------------------------------------------
extern "C" void kernel_launch(void* const* d_in, const int* in_sizes, int n_in,
                              void* d_out, int out_size) {
    const float* x    = (const float*)d_in[0];   // [2048, 7168]
    const float* qr   = (const float*)d_in[1];   // [2048, 1536]
    const float* cosv = (const float*)d_in[2];   // [2048, 64]
    const float* sinv = (const float*)d_in[3];   // [2048, 64]
    const float* wqb  = (const float*)d_in[4];   // [1536, 8192]
    const float* wk   = (const float*)d_in[5];   // [7168, 128]
    const float* wpr  = (const float*)d_in[6];   // [7168, 64]
    const float* gam  = (const float*)d_in[7];   // [128]
    const float* bet  = (const float*)d_in[8];   // [128]
    float* out = (float*)d_out;

    float *q, *kp, *kk, *w;
    cudaGetSymbolAddress((void**)&q,  g_q);
    cudaGetSymbolAddress((void**)&kp, g_kp);
    cudaGetSymbolAddress((void**)&kk, g_k);
    cudaGetSymbolAddress((void**)&w,  g_w);

    // q = qr @ Wq   [2048 x 8192 x 1536]
    sgemm128<<<dim3(HHD / 64, TT / 128), 256>>>(qr, wqb, q, TT, HHD, QL);
    // kp = x @ Wk   [2048 x 128 x 7168]
    sgemm32<<<dim3(HD / 64, TT / 32), 256>>>(x, wk, kp, TT, HD, DIM);
    // w  = x @ Wproj [2048 x 64 x 7168]
    sgemm32<<<dim3(NH / 64, TT / 32), 256>>>(x, wpr, w, TT, NH, DIM);
    // rope q in place
    rope_q<<<TT, 256>>>(q, cosv, sinv);
    // layernorm + rope k
    ln_rope_k<<<TT, 128>>>(kp, cosv, sinv, gam, bet, kk);
    // scores
    scores_kernel<<<dim3(SQ / SKT, TT), 256>>>(q, kk, w, out);
}

// round 2
// speedup vs baseline: 1.9462x; 1.9462x over previous
#include <cuda_runtime.h>

// ---------------------------------------------------------------------------
// Problem constants
// ---------------------------------------------------------------------------
#define TT   2048      // B*S total rows
#define DIM  7168
#define NH   64        // heads
#define HD   128       // head dim
#define RD   64        // rope dims
#define QL   1536
#define HHD  8192      // NH*HD
#define SQ   1024      // sequence (per batch)
#define EPSV 1e-6f
#define SCALEV 0.08838834764831845f   // 128^-0.5

// ---------------------------------------------------------------------------
// Scratch (device globals: allocation-free, graph-capture safe)
// ---------------------------------------------------------------------------
__device__ float g_q[TT * HHD];    // 64 MB : q = qr @ Wq (then roped in place)
__device__ float g_kp[TT * HD];    // pre-LN k projection
__device__ float g_k[TT * HD];     // final k (LN + rope)
__device__ float g_w[TT * NH];     // per-head weights

// ---------------------------------------------------------------------------
// tf32 helpers
// ---------------------------------------------------------------------------
__device__ __forceinline__ unsigned f2tf(float f) {
    unsigned u;
    asm("cvt.rna.tf32.f32 %0, %1;" : "=r"(u) : "f"(f));
    return u;
}

__device__ __forceinline__ void mma_tf32(float c[4], const unsigned a[4],
                                         const unsigned b[2]) {
    asm volatile(
        "mma.sync.aligned.m16n8k8.row.col.f32.tf32.tf32.f32 "
        "{%0,%1,%2,%3}, {%4,%5,%6,%7}, {%8,%9}, {%0,%1,%2,%3};"
        : "+f"(c[0]), "+f"(c[1]), "+f"(c[2]), "+f"(c[3])
        : "r"(a[0]), "r"(a[1]), "r"(a[2]), "r"(a[3]), "r"(b[0]), "r"(b[1]));
}

// ---------------------------------------------------------------------------
// Tensor-core GEMM: C[M,N] = A[M,K] @ B[K,N], fp32 in/out via tf32 MMA.
// Block tile 128x128, K-chunk 32, 256 threads = 8 warps (2 x 4).
// Warp tile 64x32 -> 4x4 m16n8k8 mmas.
// ---------------------------------------------------------------------------
#define AST 36    // As row stride (32 + 4)
#define BST 136   // Bs row stride (128 + 8)

__global__ __launch_bounds__(256) void tc_gemm(const float* __restrict__ A,
                                               const float* __restrict__ B,
                                               float* __restrict__ C,
                                               int M, int N, int K) {
    __shared__ unsigned As[128][AST];   // [m][k]
    __shared__ unsigned Bs[32][BST];    // [k][n]

    const int tid    = threadIdx.x;
    const int lane   = tid & 31;
    const int wid    = tid >> 5;
    const int warp_m = wid >> 2;        // 0..1
    const int warp_n = wid & 3;         // 0..3
    const int g      = lane >> 2;       // 0..7
    const int qd     = lane & 3;        // 0..3
    const int m0     = blockIdx.y * 128;
    const int n0     = blockIdx.x * 128;

    float acc[4][4][4];
#pragma unroll
    for (int i = 0; i < 4; i++)
#pragma unroll
        for (int j = 0; j < 4; j++)
#pragma unroll
            for (int r = 0; r < 4; r++) acc[i][j][r] = 0.f;

    for (int kt = 0; kt < K; kt += 32) {
        // A tile 128x32 -> As[m][k]  (1024 float4, 4 per thread)
#pragma unroll
        for (int r = 0; r < 4; r++) {
            int lin = r * 256 + tid;
            int row = lin >> 3, c4 = lin & 7;
            float4 v = *(const float4*)(A + (size_t)(m0 + row) * K + kt + c4 * 4);
            unsigned* p = &As[row][c4 * 4];
            p[0] = f2tf(v.x); p[1] = f2tf(v.y); p[2] = f2tf(v.z); p[3] = f2tf(v.w);
        }
        // B tile 32x128 -> Bs[k][n]
#pragma unroll
        for (int r = 0; r < 4; r++) {
            int lin = r * 256 + tid;
            int row = lin >> 5, c4 = lin & 31;
            float4 v = *(const float4*)(B + (size_t)(kt + row) * N + n0 + c4 * 4);
            unsigned* p = &Bs[row][c4 * 4];
            p[0] = f2tf(v.x); p[1] = f2tf(v.y); p[2] = f2tf(v.z); p[3] = f2tf(v.w);
        }
        __syncthreads();

#pragma unroll
        for (int k8 = 0; k8 < 4; k8++) {
            unsigned a[4][4], b[4][2];
#pragma unroll
            for (int mt = 0; mt < 4; mt++) {
                int mrow = warp_m * 64 + mt * 16 + g;
                a[mt][0] = As[mrow][k8 * 8 + qd];
                a[mt][1] = As[mrow + 8][k8 * 8 + qd];
                a[mt][2] = As[mrow][k8 * 8 + qd + 4];
                a[mt][3] = As[mrow + 8][k8 * 8 + qd + 4];
            }
#pragma unroll
            for (int nt = 0; nt < 4; nt++) {
                int ncol = warp_n * 32 + nt * 8 + g;
                b[nt][0] = Bs[k8 * 8 + qd][ncol];
                b[nt][1] = Bs[k8 * 8 + qd + 4][ncol];
            }
#pragma unroll
            for (int mt = 0; mt < 4; mt++)
#pragma unroll
                for (int nt = 0; nt < 4; nt++) mma_tf32(acc[mt][nt], a[mt], b[nt]);
        }
        __syncthreads();
    }

#pragma unroll
    for (int mt = 0; mt < 4; mt++) {
        int r0 = m0 + warp_m * 64 + mt * 16 + g;
#pragma unroll
        for (int nt = 0; nt < 4; nt++) {
            int c0 = n0 + warp_n * 32 + nt * 8 + qd * 2;
            *(float2*)(C + (size_t)r0 * N + c0)       = make_float2(acc[mt][nt][0], acc[mt][nt][1]);
            *(float2*)(C + (size_t)(r0 + 8) * N + c0) = make_float2(acc[mt][nt][2], acc[mt][nt][3]);
        }
    }
}

// ---------------------------------------------------------------------------
// SGEMM  BM=32, BN=64 (skinny k/w projections, stays fp32)
// ---------------------------------------------------------------------------
__global__ __launch_bounds__(256) void sgemm32(const float* __restrict__ A,
                                               const float* __restrict__ B,
                                               float* __restrict__ C,
                                               int M, int N, int K) {
    __shared__ float As[16][32 + 4];
    __shared__ float Bs[16][64];

    const int tid = threadIdx.x;
    const int m0  = blockIdx.y * 32;
    const int n0  = blockIdx.x * 64;
    const int ty  = tid >> 4;
    const int tx  = tid & 15;

    float acc[2][4];
#pragma unroll
    for (int i = 0; i < 2; i++)
#pragma unroll
        for (int j = 0; j < 4; j++) acc[i][j] = 0.f;

    for (int kt = 0; kt < K; kt += 16) {
        if (tid < 128) {
            int row = tid >> 2, c4 = tid & 3;
            float4 v = *(const float4*)(A + (size_t)(m0 + row) * K + kt + c4 * 4);
            As[c4 * 4 + 0][row] = v.x;
            As[c4 * 4 + 1][row] = v.y;
            As[c4 * 4 + 2][row] = v.z;
            As[c4 * 4 + 3][row] = v.w;
        }
        {
            int row = tid >> 4, c4 = tid & 15;
            float4 v = *(const float4*)(B + (size_t)(kt + row) * N + n0 + c4 * 4);
            *(float4*)&Bs[row][c4 * 4] = v;
        }
        __syncthreads();

#pragma unroll
        for (int kk = 0; kk < 16; kk++) {
            float2 a0 = *(const float2*)&As[kk][ty * 2];
            float4 b0 = *(const float4*)&Bs[kk][tx * 4];
            float a[2] = {a0.x, a0.y};
            float b[4] = {b0.x, b0.y, b0.z, b0.w};
#pragma unroll
            for (int i = 0; i < 2; i++)
#pragma unroll
                for (int j = 0; j < 4; j++) acc[i][j] = fmaf(a[i], b[j], acc[i][j]);
        }
        __syncthreads();
    }

#pragma unroll
    for (int i = 0; i < 2; i++) {
        float4 v = make_float4(acc[i][0], acc[i][1], acc[i][2], acc[i][3]);
        *(float4*)(C + (size_t)(m0 + ty * 2 + i) * N + n0 + tx * 4) = v;
    }
}

// ---------------------------------------------------------------------------
// In-place interleaved RoPE on q (first RD dims of each head).
// ---------------------------------------------------------------------------
__global__ __launch_bounds__(256) void rope_q(float* __restrict__ q,
                                              const float* __restrict__ cosv,
                                              const float* __restrict__ sinv) {
    const int t = blockIdx.x;
    const float* ct = cosv + t * RD;
    const float* st = sinv + t * RD;
    float* qt = q + (size_t)t * HHD;
#pragma unroll
    for (int it = 0; it < 8; it++) {
        int p = it * 256 + threadIdx.x;
        int h = p >> 5;
        int i = p & 31;
        float c = ct[2 * i];
        float s = st[2 * i];
        float2* addr = (float2*)(qt + h * HD + 2 * i);
        float2 v = *addr;
        *addr = make_float2(v.x * c - v.y * s, v.y * c + v.x * s);
    }
}

// ---------------------------------------------------------------------------
// LayerNorm(kp) * gamma + beta, then interleaved RoPE on first RD dims -> g_k
// ---------------------------------------------------------------------------
__global__ __launch_bounds__(128) void ln_rope_k(const float* __restrict__ kp,
                                                 const float* __restrict__ cosv,
                                                 const float* __restrict__ sinv,
                                                 const float* __restrict__ gamma,
                                                 const float* __restrict__ beta,
                                                 float* __restrict__ kout) {
    const int t = blockIdx.x;
    const int d = threadIdx.x;
    float v = kp[t * HD + d];
    float s1 = v, s2 = v * v;
#pragma unroll
    for (int off = 16; off; off >>= 1) {
        s1 += __shfl_xor_sync(0xffffffffu, s1, off);
        s2 += __shfl_xor_sync(0xffffffffu, s2, off);
    }
    __shared__ float r1[4], r2[4];
    if ((d & 31) == 0) { r1[d >> 5] = s1; r2[d >> 5] = s2; }
    __syncthreads();
    float sum = r1[0] + r1[1] + r1[2] + r1[3];
    float sq  = r2[0] + r2[1] + r2[2] + r2[3];
    float mu  = sum * (1.f / HD);
    float var = sq * (1.f / HD) - mu * mu;
    float kn  = (v - mu) * rsqrtf(var + EPSV) * gamma[d] + beta[d];

    __shared__ float ks[HD];
    ks[d] = kn;
    __syncthreads();
    float out = kn;
    if (d < RD) {
        float c = cosv[t * RD + (d & ~1)];
        float s = sinv[t * RD + (d & ~1)];
        float partner = ks[d ^ 1];
        out = ((d & 1) == 0) ? (kn * c - partner * s)
                             : (kn * c + partner * s);
    }
    kout[t * HD + d] = out;
}

// ---------------------------------------------------------------------------
// scores[b,i,k] = scale * sum_h w[b,i,h] * relu( q[b,i,h,:] . k[b,k,:] )
// Tensor-core version. Block = 2 queries (m=128 rows = 2x64 heads) x 128 keys.
// Warp (warp_m, warp_n): warp_m = query within pair, warp_n = 32-key strip.
// Per-warp head reduction is a pure shfl (rows of a query live in one warp).
// ---------------------------------------------------------------------------
__global__ __launch_bounds__(256) void scores_tc(const float* __restrict__ q,
                                                 const float* __restrict__ k,
                                                 const float* __restrict__ w,
                                                 float* __restrict__ out) {
    __shared__ unsigned Qs[128][AST];   // [m][d]  m = (query_in_pair*64 + head)
    __shared__ unsigned Ks[32][BST];    // [d][key]

    const int tid    = threadIdx.x;
    const int lane   = tid & 31;
    const int wid    = tid >> 5;
    const int warp_m = wid >> 2;        // 0..1  query within pair
    const int warp_n = wid & 3;         // 0..3  key strip
    const int g      = lane >> 2;
    const int qd     = lane & 3;

    const int pair = blockIdx.y;        // 0..1023
    const int t0   = pair * 2;
    const int b    = t0 >> 10;
    const int k0   = blockIdx.x * 128;

    // per-lane head weights (heads mt*16+g and mt*16+g+8 of this warp's query)
    const float* wrow = w + (size_t)(t0 + warp_m) * NH;
    float w0[4], w1[4];
#pragma unroll
    for (int mt = 0; mt < 4; mt++) {
        w0[mt] = wrow[mt * 16 + g] * SCALEV;
        w1[mt] = wrow[mt * 16 + g + 8] * SCALEV;
    }

    float acc[4][4][4];
#pragma unroll
    for (int i = 0; i < 4; i++)
#pragma unroll
        for (int j = 0; j < 4; j++)
#pragma unroll
            for (int r = 0; r < 4; r++) acc[i][j][r] = 0.f;

    const float* kbase = k + (size_t)(b * SQ + k0) * HD;

    for (int d0 = 0; d0 < HD; d0 += 32) {
        // Q tile: 128 rows (2 queries x 64 heads) x 32 d
#pragma unroll
        for (int r = 0; r < 4; r++) {
            int lin = r * 256 + tid;
            int row = lin >> 3, c4 = lin & 7;
            int query = t0 + (row >> 6);
            int head  = row & 63;
            float4 v = *(const float4*)(q + (size_t)query * HHD + head * HD + d0 + c4 * 4);
            unsigned* p = &Qs[row][c4 * 4];
            p[0] = f2tf(v.x); p[1] = f2tf(v.y); p[2] = f2tf(v.z); p[3] = f2tf(v.w);
        }
        // K tile: 128 keys x 32 d, transposed into Ks[d][key]
#pragma unroll
        for (int r = 0; r < 4; r++) {
            int lin = r * 256 + tid;
            int key = lin >> 3, c4 = lin & 7;
            float4 v = *(const float4*)(kbase + (size_t)key * HD + d0 + c4 * 4);
            Ks[c4 * 4 + 0][key] = f2tf(v.x);
            Ks[c4 * 4 + 1][key] = f2tf(v.y);
            Ks[c4 * 4 + 2][key] = f2tf(v.z);
            Ks[c4 * 4 + 3][key] = f2tf(v.w);
        }
        __syncthreads();

#pragma unroll
        for (int k8 = 0; k8 < 4; k8++) {
            unsigned a[4][4], bfr[4][2];
#pragma unroll
            for (int mt = 0; mt < 4; mt++) {
                int mrow = warp_m * 64 + mt * 16 + g;
                a[mt][0] = Qs[mrow][k8 * 8 + qd];
                a[mt][1] = Qs[mrow + 8][k8 * 8 + qd];
                a[mt][2] = Qs[mrow][k8 * 8 + qd + 4];
                a[mt][3] = Qs[mrow + 8][k8 * 8 + qd + 4];
            }
#pragma unroll
            for (int nt = 0; nt < 4; nt++) {
                int ncol = warp_n * 32 + nt * 8 + g;
                bfr[nt][0] = Ks[k8 * 8 + qd][ncol];
                bfr[nt][1] = Ks[k8 * 8 + qd + 4][ncol];
            }
#pragma unroll
            for (int mt = 0; mt < 4; mt++)
#pragma unroll
                for (int nt = 0; nt < 4; nt++) mma_tf32(acc[mt][nt], a[mt], bfr[nt]);
        }
        __syncthreads();
    }

    // weighted relu + head reduction (intra-warp)
    float p[4][2];
#pragma unroll
    for (int nt = 0; nt < 4; nt++) { p[nt][0] = 0.f; p[nt][1] = 0.f; }
#pragma unroll
    for (int mt = 0; mt < 4; mt++) {
#pragma unroll
        for (int nt = 0; nt < 4; nt++) {
            p[nt][0] += w0[mt] * fmaxf(acc[mt][nt][0], 0.f)
                      + w1[mt] * fmaxf(acc[mt][nt][2], 0.f);
            p[nt][1] += w0[mt] * fmaxf(acc[mt][nt][1], 0.f)
                      + w1[mt] * fmaxf(acc[mt][nt][3], 0.f);
        }
    }
#pragma unroll
    for (int nt = 0; nt < 4; nt++) {
#pragma unroll
        for (int off = 4; off <= 16; off <<= 1) {
            p[nt][0] += __shfl_xor_sync(0xffffffffu, p[nt][0], off);
            p[nt][1] += __shfl_xor_sync(0xffffffffu, p[nt][1], off);
        }
    }

    if (lane < 4) {
        float* o = out + (size_t)(t0 + warp_m) * SQ + k0 + warp_n * 32;
#pragma unroll
        for (int nt = 0; nt < 4; nt++) {
            *(float2*)(o + nt * 8 + lane * 2) = make_float2(p[nt][0], p[nt][1]);
        }
    }
}

// ---------------------------------------------------------------------------
// launch
// ---------------------------------------------------------------------------
extern "C" void kernel_launch(void* const* d_in, const int* in_sizes, int n_in,
                              void* d_out, int out_size) {
    const float* x    = (const float*)d_in[0];   // [2048, 7168]
    const float* qr   = (const float*)d_in[1];   // [2048, 1536]
    const float* cosv = (const float*)d_in[2];   // [2048, 64]
    const float* sinv = (const float*)d_in[3];   // [2048, 64]
    const float* wqb  = (const float*)d_in[4];   // [1536, 8192]
    const float* wk   = (const float*)d_in[5];   // [7168, 128]
    const float* wpr  = (const float*)d_in[6];   // [7168, 64]
    const float* gam  = (const float*)d_in[7];   // [128]
    const float* bet  = (const float*)d_in[8];   // [128]
    float* out = (float*)d_out;

    float *q, *kp, *kk, *w;
    cudaGetSymbolAddress((void**)&q,  g_q);
    cudaGetSymbolAddress((void**)&kp, g_kp);
    cudaGetSymbolAddress((void**)&kk, g_k);
    cudaGetSymbolAddress((void**)&w,  g_w);

    // q = qr @ Wq   [2048 x 8192 x 1536]  (tensor cores, tf32)
    tc_gemm<<<dim3(HHD / 128, TT / 128), 256>>>(qr, wqb, q, TT, HHD, QL);
    // kp = x @ Wk   [2048 x 128 x 7168]
    sgemm32<<<dim3(HD / 64, TT / 32), 256>>>(x, wk, kp, TT, HD, DIM);
    // w  = x @ Wproj [2048 x 64 x 7168]
    sgemm32<<<dim3(NH / 64, TT / 32), 256>>>(x, wpr, w, TT, NH, DIM);
    // rope q in place
    rope_q<<<TT, 256>>>(q, cosv, sinv);
    // layernorm + rope k
    ln_rope_k<<<TT, 128>>>(kp, cosv, sinv, gam, bet, kk);
    // scores (tensor cores, tf32)
    scores_tc<<<dim3(SQ / 128, TT / 2), 256>>>(q, kk, w, out);
}

// round 4
// speedup vs baseline: 4.5893x; 2.3581x over previous
#include <cuda_runtime.h>
#include <cstdint>

// ---------------------------------------------------------------------------
// Problem constants
// ---------------------------------------------------------------------------
#define TT   2048      // B*S total rows
#define DIM  7168
#define NH   64        // heads
#define HD   128       // head dim
#define RD   64        // rope dims
#define QL   1536
#define HHD  8192      // NH*HD
#define SQ   1024      // sequence (per batch)
#define EPSV 1e-6f
#define SCALEV 0.08838834764831845f   // 128^-0.5
#define KSPL 8         // split-K factor for the kw GEMM

// ---------------------------------------------------------------------------
// Scratch (device globals: allocation-free, graph-capture safe)
// ---------------------------------------------------------------------------
__device__ float    g_q[TT * HHD];          // 64 MB : q = qr @ Wq (roped in place)
__device__ unsigned g_wqt[HHD * QL];        // 50 MB : Wq^T tf32 bits [N][K]
__device__ unsigned g_bkw[256 * DIM];       // 7.3MB : (Wk || Wproj || 0)^T tf32 bits
__device__ float    g_kwp[KSPL * TT * 256]; // 16 MB : split-K partials
__device__ float    g_kw[TT * 256];         // kp (cols 0-127) | w (cols 128-191)
__device__ unsigned g_ktf[TT * HD];         // final k, tf32 bits

// ---------------------------------------------------------------------------
// helpers
// ---------------------------------------------------------------------------
__device__ __forceinline__ unsigned f2tf(float f) {
    unsigned u;
    asm("cvt.rna.tf32.f32 %0, %1;" : "=r"(u) : "f"(f));
    return u;
}

__device__ __forceinline__ uint32_t smem_u32(const void* p) {
    uint32_t a;
    asm("{ .reg .u64 t; cvta.to.shared.u64 t, %1; cvt.u32.u64 %0, t; }"
        : "=r"(a) : "l"(p));
    return a;
}

#define CP_ASYNC16(dst, src) \
    asm volatile("cp.async.cg.shared.global [%0], [%1], 16;" \
                 :: "r"(dst), "l"(src) : "memory")
#define CP_COMMIT() asm volatile("cp.async.commit_group;" ::: "memory")
#define CP_WAIT(n)  asm volatile("cp.async.wait_group %0;" :: "n"(n) : "memory")

__device__ __forceinline__ void mma_tf32(float c[4], const unsigned a[4],
                                         const unsigned b[2]) {
    asm volatile(
        "mma.sync.aligned.m16n8k8.row.col.f32.tf32.tf32.f32 "
        "{%0,%1,%2,%3}, {%4,%5,%6,%7}, {%8,%9}, {%0,%1,%2,%3};"
        : "+f"(c[0]), "+f"(c[1]), "+f"(c[2]), "+f"(c[3])
        : "r"(a[0]), "r"(a[1]), "r"(a[2]), "r"(a[3]), "r"(b[0]), "r"(b[1]));
}

// smem tile geometry: [128 rows][32 k + 4 pad] u32, row stride 36 u32 = 144 B
#define RST 36
#define TS_B_OFF 18432                     // 128*144
#define STAGE_BYTES 36864                  // A + B tile per stage
#define SMEM_PIPE (2 * STAGE_BYTES)        // 73728

// ---------------------------------------------------------------------------
// Transpose + tf32-convert:  Wqt[n][k] = tf32(Wq[k][n])
// ---------------------------------------------------------------------------
__global__ __launch_bounds__(256) void transpose_tf(const float* __restrict__ W,
                                                    unsigned* __restrict__ Wt) {
    __shared__ float tile[32][33];
    const int tx = threadIdx.x, ty = threadIdx.y;
    const int n0 = blockIdx.x * 32, k0 = blockIdx.y * 32;
#pragma unroll
    for (int j = 0; j < 32; j += 8)
        tile[ty + j][tx] = W[(size_t)(k0 + ty + j) * HHD + n0 + tx];
    __syncthreads();
#pragma unroll
    for (int j = 0; j < 32; j += 8)
        Wt[(size_t)(n0 + ty + j) * QL + k0 + tx] = f2tf(tile[tx][ty + j]);
}

// ---------------------------------------------------------------------------
// Pack (Wk || Wproj || 0) transposed -> g_bkw[n][k], tf32 bits.  n in [0,256)
// ---------------------------------------------------------------------------
__global__ __launch_bounds__(256) void pack_kw(const float* __restrict__ wk,
                                               const float* __restrict__ wpr,
                                               unsigned* __restrict__ Bkw) {
    __shared__ float tile[32][33];
    const int tx = threadIdx.x, ty = threadIdx.y;
    const int n0 = blockIdx.x * 32, k0 = blockIdx.y * 32;
#pragma unroll
    for (int j = 0; j < 32; j += 8) {
        int k = k0 + ty + j, n = n0 + tx;
        float v = (n < HD) ? wk[(size_t)k * HD + n]
                           : ((n < HD + NH) ? wpr[(size_t)k * NH + (n - HD)] : 0.f);
        tile[ty + j][tx] = v;
    }
    __syncthreads();
#pragma unroll
    for (int j = 0; j < 32; j += 8)
        Bkw[(size_t)(n0 + ty + j) * DIM + k0 + tx] = f2tf(tile[tx][ty + j]);
}

// ---------------------------------------------------------------------------
// Double-buffered mma.sync tf32 GEMM.
// C[M,N] (+ split-K partials along gridDim.z) = A[M,Ktot] @ B[N,Ktot]^T
// A fp32 (converted in-register), B pre-converted tf32 bits.
// Block tile 128x128, 8 warps (2x4), warp tile 64x32, K chunk 32.
// ---------------------------------------------------------------------------
__global__ __launch_bounds__(256) void tc_mma_gemm(const float* __restrict__ A,
                                                   const unsigned* __restrict__ B,
                                                   float* __restrict__ C,
                                                   int Ktot, int N, int nchunks) {
    extern __shared__ char smem[];
    const uint32_t sb = smem_u32(smem);
    const int tid = threadIdx.x;
    const int lane = tid & 31, wid = tid >> 5;
    const int warp_m = wid >> 2, warp_n = wid & 3;
    const int g = lane >> 2, qd = lane & 3;
    const int m0 = blockIdx.y * 128;
    const int n0 = blockIdx.x * 128;
    const int c0 = blockIdx.z * nchunks;
    C += (size_t)blockIdx.z * gridDim.y * 128 * N;

    auto load_stage = [&](int c, int s) {
        const int kt = c * 32;
        const uint32_t base = sb + s * STAGE_BYTES;
#pragma unroll
        for (int r = 0; r < 4; r++) {
            int lin = r * 256 + tid;
            int row = lin >> 3, c4 = lin & 7;
            CP_ASYNC16(base + row * 144 + c4 * 16,
                       A + (size_t)(m0 + row) * Ktot + kt + c4 * 4);
        }
#pragma unroll
        for (int r = 0; r < 4; r++) {
            int lin = r * 256 + tid;
            int row = lin >> 3, c4 = lin & 7;
            CP_ASYNC16(base + TS_B_OFF + row * 144 + c4 * 16,
                       B + (size_t)(n0 + row) * Ktot + kt + c4 * 4);
        }
        CP_COMMIT();
    };

    float acc[4][4][4];
#pragma unroll
    for (int i = 0; i < 4; i++)
#pragma unroll
        for (int j = 0; j < 4; j++)
#pragma unroll
            for (int r = 0; r < 4; r++) acc[i][j][r] = 0.f;

    load_stage(c0, 0);

    for (int i = 0; i < nchunks; i++) {
        const int s = i & 1;
        if (i + 1 < nchunks) { load_stage(c0 + i + 1, s ^ 1); CP_WAIT(1); }
        else                 { CP_WAIT(0); }
        __syncthreads();

        const unsigned* As = (const unsigned*)(smem + s * STAGE_BYTES);
        const unsigned* Bs = (const unsigned*)(smem + s * STAGE_BYTES + TS_B_OFF);
#pragma unroll
        for (int k8 = 0; k8 < 4; k8++) {
            unsigned a[4][4], b[4][2];
#pragma unroll
            for (int mt = 0; mt < 4; mt++) {
                int mrow = warp_m * 64 + mt * 16 + g;
                a[mt][0] = f2tf(__uint_as_float(As[mrow * RST + k8 * 8 + qd]));
                a[mt][1] = f2tf(__uint_as_float(As[(mrow + 8) * RST + k8 * 8 + qd]));
                a[mt][2] = f2tf(__uint_as_float(As[mrow * RST + k8 * 8 + qd + 4]));
                a[mt][3] = f2tf(__uint_as_float(As[(mrow + 8) * RST + k8 * 8 + qd + 4]));
            }
#pragma unroll
            for (int nt = 0; nt < 4; nt++) {
                int ncol = warp_n * 32 + nt * 8 + g;
                b[nt][0] = Bs[ncol * RST + k8 * 8 + qd];
                b[nt][1] = Bs[ncol * RST + k8 * 8 + qd + 4];
            }
#pragma unroll
            for (int mt = 0; mt < 4; mt++)
#pragma unroll
                for (int nt = 0; nt < 4; nt++) mma_tf32(acc[mt][nt], a[mt], b[nt]);
        }
        __syncthreads();
    }

#pragma unroll
    for (int mt = 0; mt < 4; mt++) {
        int r0 = m0 + warp_m * 64 + mt * 16 + g;
#pragma unroll
        for (int nt = 0; nt < 4; nt++) {
            int cc = n0 + warp_n * 32 + nt * 8 + qd * 2;
            *(float2*)(C + (size_t)r0 * N + cc)       = make_float2(acc[mt][nt][0], acc[mt][nt][1]);
            *(float2*)(C + (size_t)(r0 + 8) * N + cc) = make_float2(acc[mt][nt][2], acc[mt][nt][3]);
        }
    }
}

// ---------------------------------------------------------------------------
// Reduce split-K partials: g_kw = sum_z g_kwp[z]
// ---------------------------------------------------------------------------
__global__ __launch_bounds__(256) void reduce_kw(const float* __restrict__ part,
                                                 float* __restrict__ outb) {
    const int i4 = blockIdx.x * 256 + threadIdx.x;   // float4 index
    const size_t SZ = (size_t)TT * 256;
    float4 s = *(const float4*)(part + (size_t)i4 * 4);
#pragma unroll
    for (int z = 1; z < KSPL; z++) {
        float4 v = *(const float4*)(part + z * SZ + (size_t)i4 * 4);
        s.x += v.x; s.y += v.y; s.z += v.z; s.w += v.w;
    }
    *(float4*)(outb + (size_t)i4 * 4) = s;
}

// ---------------------------------------------------------------------------
// In-place interleaved RoPE on q (first RD dims of each head).
// ---------------------------------------------------------------------------
__global__ __launch_bounds__(256) void rope_q(float* __restrict__ q,
                                              const float* __restrict__ cosv,
                                              const float* __restrict__ sinv) {
    const int t = blockIdx.x;
    const float* ct = cosv + t * RD;
    const float* st = sinv + t * RD;
    float* qt = q + (size_t)t * HHD;
#pragma unroll
    for (int it = 0; it < 8; it++) {
        int p = it * 256 + threadIdx.x;
        int h = p >> 5;
        int i = p & 31;
        float c = ct[2 * i];
        float s = st[2 * i];
        float2* addr = (float2*)(qt + h * HD + 2 * i);
        float2 v = *addr;
        *addr = make_float2(v.x * c - v.y * s, v.y * c + v.x * s);
    }
}

// ---------------------------------------------------------------------------
// LayerNorm(kp)*gamma+beta, RoPE on first RD dims, output tf32 bits -> g_ktf
// kp read from g_kw with row stride 256.
// ---------------------------------------------------------------------------
__global__ __launch_bounds__(128) void ln_rope_k(const float* __restrict__ kw,
                                                 const float* __restrict__ cosv,
                                                 const float* __restrict__ sinv,
                                                 const float* __restrict__ gamma,
                                                 const float* __restrict__ beta,
                                                 unsigned* __restrict__ kout) {
    const int t = blockIdx.x;
    const int d = threadIdx.x;
    float v = kw[(size_t)t * 256 + d];
    float s1 = v, s2 = v * v;
#pragma unroll
    for (int off = 16; off; off >>= 1) {
        s1 += __shfl_xor_sync(0xffffffffu, s1, off);
        s2 += __shfl_xor_sync(0xffffffffu, s2, off);
    }
    __shared__ float r1[4], r2[4];
    if ((d & 31) == 0) { r1[d >> 5] = s1; r2[d >> 5] = s2; }
    __syncthreads();
    float sum = r1[0] + r1[1] + r1[2] + r1[3];
    float sq  = r2[0] + r2[1] + r2[2] + r2[3];
    float mu  = sum * (1.f / HD);
    float var = sq * (1.f / HD) - mu * mu;
    float kn  = (v - mu) * rsqrtf(var + EPSV) * gamma[d] + beta[d];

    __shared__ float ks[HD];
    ks[d] = kn;
    __syncthreads();
    float out = kn;
    if (d < RD) {
        float c = cosv[t * RD + (d & ~1)];
        float s = sinv[t * RD + (d & ~1)];
        float partner = ks[d ^ 1];
        out = ((d & 1) == 0) ? (kn * c - partner * s)
                             : (kn * c + partner * s);
    }
    kout[t * HD + d] = f2tf(out);
}

// ---------------------------------------------------------------------------
// scores[b,i,k] = scale * sum_h w[b,i,h] * relu( q[b,i,h,:] . k[b,k,:] )
// Double-buffered cp.async. Block = 2 queries (128 rows) x 128 keys.
// Q fp32 (convert in-reg), K pre-converted tf32 bits.
// ---------------------------------------------------------------------------
__global__ __launch_bounds__(256) void scores_tc(const float* __restrict__ q,
                                                 const unsigned* __restrict__ ktf,
                                                 const float* __restrict__ kw,
                                                 float* __restrict__ out) {
    extern __shared__ char smem[];
    const uint32_t sb = smem_u32(smem);
    const int tid = threadIdx.x;
    const int lane = tid & 31, wid = tid >> 5;
    const int warp_m = wid >> 2, warp_n = wid & 3;
    const int g = lane >> 2, qd = lane & 3;

    const int t0 = blockIdx.y * 2;
    const int b  = t0 >> 10;
    const int k0 = blockIdx.x * 128;

    // per-lane head weights (w lives at g_kw[t*256 + 128 + h])
    const float* wrow = kw + (size_t)(t0 + warp_m) * 256 + 128;
    float w0[4], w1[4];
#pragma unroll
    for (int mt = 0; mt < 4; mt++) {
        w0[mt] = wrow[mt * 16 + g] * SCALEV;
        w1[mt] = wrow[mt * 16 + g + 8] * SCALEV;
    }

    const float*    qbase = q + (size_t)t0 * HHD;
    const unsigned* kbase = ktf + (size_t)(b * SQ + k0) * HD;

    auto load_stage = [&](int c, int s) {
        const int d0 = c * 32;
        const uint32_t base = sb + s * STAGE_BYTES;
#pragma unroll
        for (int r = 0; r < 4; r++) {
            int lin = r * 256 + tid;
            int row = lin >> 3, c4 = lin & 7;
            CP_ASYNC16(base + row * 144 + c4 * 16,
                       qbase + (size_t)(row >> 6) * HHD + (row & 63) * HD + d0 + c4 * 4);
        }
#pragma unroll
        for (int r = 0; r < 4; r++) {
            int lin = r * 256 + tid;
            int row = lin >> 3, c4 = lin & 7;
            CP_ASYNC16(base + TS_B_OFF + row * 144 + c4 * 16,
                       kbase + (size_t)row * HD + d0 + c4 * 4);
        }
        CP_COMMIT();
    };

    float acc[4][4][4];
#pragma unroll
    for (int i = 0; i < 4; i++)
#pragma unroll
        for (int j = 0; j < 4; j++)
#pragma unroll
            for (int r = 0; r < 4; r++) acc[i][j][r] = 0.f;

    load_stage(0, 0);

#pragma unroll
    for (int i = 0; i < 4; i++) {
        const int s = i & 1;
        if (i + 1 < 4) { load_stage(i + 1, s ^ 1); CP_WAIT(1); }
        else           { CP_WAIT(0); }
        __syncthreads();

        const unsigned* Qs = (const unsigned*)(smem + s * STAGE_BYTES);
        const unsigned* Ks = (const unsigned*)(smem + s * STAGE_BYTES + TS_B_OFF);
#pragma unroll
        for (int k8 = 0; k8 < 4; k8++) {
            unsigned a[4][4], bfr[4][2];
#pragma unroll
            for (int mt = 0; mt < 4; mt++) {
                int mrow = warp_m * 64 + mt * 16 + g;
                a[mt][0] = f2tf(__uint_as_float(Qs[mrow * RST + k8 * 8 + qd]));
                a[mt][1] = f2tf(__uint_as_float(Qs[(mrow + 8) * RST + k8 * 8 + qd]));
                a[mt][2] = f2tf(__uint_as_float(Qs[mrow * RST + k8 * 8 + qd + 4]));
                a[mt][3] = f2tf(__uint_as_float(Qs[(mrow + 8) * RST + k8 * 8 + qd + 4]));
            }
#pragma unroll
            for (int nt = 0; nt < 4; nt++) {
                int ncol = warp_n * 32 + nt * 8 + g;
                bfr[nt][0] = Ks[ncol * RST + k8 * 8 + qd];
                bfr[nt][1] = Ks[ncol * RST + k8 * 8 + qd + 4];
            }
#pragma unroll
            for (int mt = 0; mt < 4; mt++)
#pragma unroll
                for (int nt = 0; nt < 4; nt++) mma_tf32(acc[mt][nt], a[mt], bfr[nt]);
        }
        __syncthreads();
    }

    // weighted relu + head reduction (intra-warp shfl)
    float p[4][2];
#pragma unroll
    for (int nt = 0; nt < 4; nt++) { p[nt][0] = 0.f; p[nt][1] = 0.f; }
#pragma unroll
    for (int mt = 0; mt < 4; mt++) {
#pragma unroll
        for (int nt = 0; nt < 4; nt++) {
            p[nt][0] += w0[mt] * fmaxf(acc[mt][nt][0], 0.f)
                      + w1[mt] * fmaxf(acc[mt][nt][2], 0.f);
            p[nt][1] += w0[mt] * fmaxf(acc[mt][nt][1], 0.f)
                      + w1[mt] * fmaxf(acc[mt][nt][3], 0.f);
        }
    }
#pragma unroll
    for (int nt = 0; nt < 4; nt++) {
#pragma unroll
        for (int off = 4; off <= 16; off <<= 1) {
            p[nt][0] += __shfl_xor_sync(0xffffffffu, p[nt][0], off);
            p[nt][1] += __shfl_xor_sync(0xffffffffu, p[nt][1], off);
        }
    }

    if (lane < 4) {
        float* o = out + (size_t)(t0 + warp_m) * SQ + k0 + warp_n * 32;
#pragma unroll
        for (int nt = 0; nt < 4; nt++)
            *(float2*)(o + nt * 8 + lane * 2) = make_float2(p[nt][0], p[nt][1]);
    }
}

// ---------------------------------------------------------------------------
// launch
// ---------------------------------------------------------------------------
extern "C" void kernel_launch(void* const* d_in, const int* in_sizes, int n_in,
                              void* d_out, int out_size) {
    const float* x    = (const float*)d_in[0];   // [2048, 7168]
    const float* qr   = (const float*)d_in[1];   // [2048, 1536]
    const float* cosv = (const float*)d_in[2];   // [2048, 64]
    const float* sinv = (const float*)d_in[3];   // [2048, 64]
    const float* wqb  = (const float*)d_in[4];   // [1536, 8192]
    const float* wk   = (const float*)d_in[5];   // [7168, 128]
    const float* wpr  = (const float*)d_in[6];   // [7168, 64]
    const float* gam  = (const float*)d_in[7];   // [128]
    const float* bet  = (const float*)d_in[8];   // [128]
    float* out = (float*)d_out;

    float *q, *kwp, *kwb;
    unsigned *wqt, *bkw, *ktf;
    cudaGetSymbolAddress((void**)&q,   g_q);
    cudaGetSymbolAddress((void**)&wqt, g_wqt);
    cudaGetSymbolAddress((void**)&bkw, g_bkw);
    cudaGetSymbolAddress((void**)&kwp, g_kwp);
    cudaGetSymbolAddress((void**)&kwb, g_kw);
    cudaGetSymbolAddress((void**)&ktf, g_ktf);

    static bool attr_set = false;
    if (!attr_set) {
        cudaFuncSetAttribute(tc_mma_gemm, cudaFuncAttributeMaxDynamicSharedMemorySize, SMEM_PIPE);
        cudaFuncSetAttribute(scores_tc,  cudaFuncAttributeMaxDynamicSharedMemorySize, SMEM_PIPE);
        attr_set = true;
    }

    // B-operand prep (tf32 bits, transposed)
    transpose_tf<<<dim3(HHD / 32, QL / 32), dim3(32, 8)>>>(wqb, wqt);
    pack_kw<<<dim3(8, DIM / 32), dim3(32, 8)>>>(wk, wpr, bkw);

    // q = qr @ Wq   [2048 x 8192 x 1536]
    tc_mma_gemm<<<dim3(HHD / 128, TT / 128, 1), 256, SMEM_PIPE>>>(qr, wqt, q, QL, HHD, QL / 32);
    // kp|w = x @ (Wk||Wproj)  split-K=8 partials, then reduce
    tc_mma_gemm<<<dim3(2, TT / 128, KSPL), 256, SMEM_PIPE>>>(x, bkw, kwp, DIM, 256, DIM / 32 / KSPL);
    reduce_kw<<<(TT * 256 / 4) / 256, 256>>>(kwp, kwb);

    // rope q in place
    rope_q<<<TT, 256>>>(q, cosv, sinv);
    // layernorm + rope k -> tf32 bits
    ln_rope_k<<<TT, 128>>>(kwb, cosv, sinv, gam, bet, ktf);
    // scores
    scores_tc<<<dim3(SQ / 128, TT / 2), 256, SMEM_PIPE>>>(q, ktf, kwb, out);
}

// round 5
// speedup vs baseline: 4.8259x; 1.0516x over previous
#include <cuda_runtime.h>
#include <cstdint>

// ---------------------------------------------------------------------------
// Problem constants
// ---------------------------------------------------------------------------
#define TT   2048      // B*S total rows
#define DIM  7168
#define NH   64        // heads
#define HD   128       // head dim
#define RD   64        // rope dims
#define QL   1536
#define HHD  8192      // NH*HD
#define SQ   1024      // sequence (per batch)
#define EPSV 1e-6f
#define SCALEV 0.08838834764831845f   // 128^-0.5
#define KSPL 8         // split-K factor for the kw GEMM

// ---------------------------------------------------------------------------
// Scratch (device globals: allocation-free, graph-capture safe)
// ---------------------------------------------------------------------------
__device__ float    g_q[TT * HHD];          // 64 MB : q = qr @ Wq (tf32 bits after rope)
__device__ unsigned g_qrt[TT * QL];         // 12.6MB: qr tf32 bits
__device__ unsigned g_xt[TT * DIM];         // 58 MB : x  tf32 bits
__device__ unsigned g_wqt[HHD * QL];        // 50 MB : Wq^T tf32 bits [N][K]
__device__ unsigned g_bkw[256 * DIM];       // 7.3MB : (Wk || Wproj || 0)^T tf32 bits
__device__ float    g_kwp[KSPL * TT * 256]; // 16 MB : split-K partials
__device__ float    g_kw[TT * 256];         // kp (cols 0-127) | w (cols 128-191)
__device__ unsigned g_ktf[TT * HD];         // final k, tf32 bits

// ---------------------------------------------------------------------------
// helpers
// ---------------------------------------------------------------------------
__device__ __forceinline__ unsigned f2tf(float f) {
    unsigned u;
    asm("cvt.rna.tf32.f32 %0, %1;" : "=r"(u) : "f"(f));
    return u;
}

__device__ __forceinline__ uint32_t smem_u32(const void* p) {
    uint32_t a;
    asm("{ .reg .u64 t; cvta.to.shared.u64 t, %1; cvt.u32.u64 %0, t; }"
        : "=r"(a) : "l"(p));
    return a;
}

#define CP_ASYNC16(dst, src) \
    asm volatile("cp.async.cg.shared.global [%0], [%1], 16;" \
                 :: "r"(dst), "l"(src) : "memory")
#define CP_COMMIT() asm volatile("cp.async.commit_group;" ::: "memory")
#define CP_WAIT(n)  asm volatile("cp.async.wait_group %0;" :: "n"(n) : "memory")

__device__ __forceinline__ void mma_tf32(float c[4], const unsigned a[4],
                                         const unsigned b[2]) {
    asm volatile(
        "mma.sync.aligned.m16n8k8.row.col.f32.tf32.tf32.f32 "
        "{%0,%1,%2,%3}, {%4,%5,%6,%7}, {%8,%9}, {%0,%1,%2,%3};"
        : "+f"(c[0]), "+f"(c[1]), "+f"(c[2]), "+f"(c[3])
        : "r"(a[0]), "r"(a[1]), "r"(a[2]), "r"(a[3]), "r"(b[0]), "r"(b[1]));
}

// smem tile geometry: [128 rows][32 k + 4 pad] u32, row stride 36 u32 = 144 B
#define RST 36
#define TS_B_OFF 18432                     // 128*144
#define STAGE_BYTES 36864                  // A + B tile per stage
#define SMEM_PIPE (2 * STAGE_BYTES)        // 73728

// ---------------------------------------------------------------------------
// Elementwise fp32 -> tf32 bits (float4 granularity)
// ---------------------------------------------------------------------------
__global__ __launch_bounds__(256) void cvt_tf(const float* __restrict__ in,
                                              unsigned* __restrict__ outb) {
    const size_t i4 = (size_t)blockIdx.x * 256 + threadIdx.x;
    float4 v = *(const float4*)(in + i4 * 4);
    uint4 t;
    t.x = f2tf(v.x); t.y = f2tf(v.y); t.z = f2tf(v.z); t.w = f2tf(v.w);
    *(uint4*)(outb + i4 * 4) = t;
}

// ---------------------------------------------------------------------------
// Transpose + tf32-convert:  Wqt[n][k] = tf32(Wq[k][n])
// ---------------------------------------------------------------------------
__global__ __launch_bounds__(256) void transpose_tf(const float* __restrict__ W,
                                                    unsigned* __restrict__ Wt) {
    __shared__ float tile[32][33];
    const int tx = threadIdx.x, ty = threadIdx.y;
    const int n0 = blockIdx.x * 32, k0 = blockIdx.y * 32;
#pragma unroll
    for (int j = 0; j < 32; j += 8)
        tile[ty + j][tx] = W[(size_t)(k0 + ty + j) * HHD + n0 + tx];
    __syncthreads();
#pragma unroll
    for (int j = 0; j < 32; j += 8)
        Wt[(size_t)(n0 + ty + j) * QL + k0 + tx] = f2tf(tile[tx][ty + j]);
}

// ---------------------------------------------------------------------------
// Pack (Wk || Wproj || 0) transposed -> g_bkw[n][k], tf32 bits.  n in [0,256)
// ---------------------------------------------------------------------------
__global__ __launch_bounds__(256) void pack_kw(const float* __restrict__ wk,
                                               const float* __restrict__ wpr,
                                               unsigned* __restrict__ Bkw) {
    __shared__ float tile[32][33];
    const int tx = threadIdx.x, ty = threadIdx.y;
    const int n0 = blockIdx.x * 32, k0 = blockIdx.y * 32;
#pragma unroll
    for (int j = 0; j < 32; j += 8) {
        int k = k0 + ty + j, n = n0 + tx;
        float v = (n < HD) ? wk[(size_t)k * HD + n]
                           : ((n < HD + NH) ? wpr[(size_t)k * NH + (n - HD)] : 0.f);
        tile[ty + j][tx] = v;
    }
    __syncthreads();
#pragma unroll
    for (int j = 0; j < 32; j += 8)
        Bkw[(size_t)(n0 + ty + j) * DIM + k0 + tx] = f2tf(tile[tx][ty + j]);
}

// ---------------------------------------------------------------------------
// Double-buffered mma.sync tf32 GEMM, all operands pre-converted tf32 bits.
// C[M,N] (+ split-K partials along gridDim.z) = A[M,Ktot] @ B[N,Ktot]^T
// Block tile 128x128, 8 warps (2x4), warp tile 64x32, K chunk 32. 2 CTAs/SM.
// ---------------------------------------------------------------------------
__global__ __launch_bounds__(256, 2) void tc_mma_gemm(const unsigned* __restrict__ A,
                                                      const unsigned* __restrict__ B,
                                                      float* __restrict__ C,
                                                      int Ktot, int N, int nchunks) {
    extern __shared__ char smem[];
    const uint32_t sb = smem_u32(smem);
    const int tid = threadIdx.x;
    const int lane = tid & 31, wid = tid >> 5;
    const int warp_m = wid >> 2, warp_n = wid & 3;
    const int g = lane >> 2, qd = lane & 3;
    const int m0 = blockIdx.y * 128;
    const int n0 = blockIdx.x * 128;
    const int c0 = blockIdx.z * nchunks;
    C += (size_t)blockIdx.z * gridDim.y * 128 * N;

    auto load_stage = [&](int c, int s) {
        const int kt = c * 32;
        const uint32_t base = sb + s * STAGE_BYTES;
#pragma unroll
        for (int r = 0; r < 4; r++) {
            int lin = r * 256 + tid;
            int row = lin >> 3, c4 = lin & 7;
            CP_ASYNC16(base + row * 144 + c4 * 16,
                       A + (size_t)(m0 + row) * Ktot + kt + c4 * 4);
        }
#pragma unroll
        for (int r = 0; r < 4; r++) {
            int lin = r * 256 + tid;
            int row = lin >> 3, c4 = lin & 7;
            CP_ASYNC16(base + TS_B_OFF + row * 144 + c4 * 16,
                       B + (size_t)(n0 + row) * Ktot + kt + c4 * 4);
        }
        CP_COMMIT();
    };

    float acc[4][4][4];
#pragma unroll
    for (int i = 0; i < 4; i++)
#pragma unroll
        for (int j = 0; j < 4; j++)
#pragma unroll
            for (int r = 0; r < 4; r++) acc[i][j][r] = 0.f;

    load_stage(c0, 0);

    for (int i = 0; i < nchunks; i++) {
        const int s = i & 1;
        if (i + 1 < nchunks) { load_stage(c0 + i + 1, s ^ 1); CP_WAIT(1); }
        else                 { CP_WAIT(0); }
        __syncthreads();

        const unsigned* As = (const unsigned*)(smem + s * STAGE_BYTES);
        const unsigned* Bs = (const unsigned*)(smem + s * STAGE_BYTES + TS_B_OFF);
#pragma unroll
        for (int k8 = 0; k8 < 4; k8++) {
            unsigned a[4][4], b[4][2];
#pragma unroll
            for (int mt = 0; mt < 4; mt++) {
                int mrow = warp_m * 64 + mt * 16 + g;
                a[mt][0] = As[mrow * RST + k8 * 8 + qd];
                a[mt][1] = As[(mrow + 8) * RST + k8 * 8 + qd];
                a[mt][2] = As[mrow * RST + k8 * 8 + qd + 4];
                a[mt][3] = As[(mrow + 8) * RST + k8 * 8 + qd + 4];
            }
#pragma unroll
            for (int nt = 0; nt < 4; nt++) {
                int ncol = warp_n * 32 + nt * 8 + g;
                b[nt][0] = Bs[ncol * RST + k8 * 8 + qd];
                b[nt][1] = Bs[ncol * RST + k8 * 8 + qd + 4];
            }
#pragma unroll
            for (int mt = 0; mt < 4; mt++)
#pragma unroll
                for (int nt = 0; nt < 4; nt++) mma_tf32(acc[mt][nt], a[mt], b[nt]);
        }
        __syncthreads();
    }

#pragma unroll
    for (int mt = 0; mt < 4; mt++) {
        int r0 = m0 + warp_m * 64 + mt * 16 + g;
#pragma unroll
        for (int nt = 0; nt < 4; nt++) {
            int cc = n0 + warp_n * 32 + nt * 8 + qd * 2;
            *(float2*)(C + (size_t)r0 * N + cc)       = make_float2(acc[mt][nt][0], acc[mt][nt][1]);
            *(float2*)(C + (size_t)(r0 + 8) * N + cc) = make_float2(acc[mt][nt][2], acc[mt][nt][3]);
        }
    }
}

// ---------------------------------------------------------------------------
// Reduce split-K partials: g_kw = sum_z g_kwp[z]
// ---------------------------------------------------------------------------
__global__ __launch_bounds__(256) void reduce_kw(const float* __restrict__ part,
                                                 float* __restrict__ outb) {
    const int i4 = blockIdx.x * 256 + threadIdx.x;
    const size_t SZ = (size_t)TT * 256;
    float4 s = *(const float4*)(part + (size_t)i4 * 4);
#pragma unroll
    for (int z = 1; z < KSPL; z++) {
        float4 v = *(const float4*)(part + z * SZ + (size_t)i4 * 4);
        s.x += v.x; s.y += v.y; s.z += v.z; s.w += v.w;
    }
    *(float4*)(outb + (size_t)i4 * 4) = s;
}

// ---------------------------------------------------------------------------
// In-place RoPE on q + whole-row tf32 conversion (q becomes tf32 bits).
// ---------------------------------------------------------------------------
__global__ __launch_bounds__(256) void rope_q(float* __restrict__ q,
                                              const float* __restrict__ cosv,
                                              const float* __restrict__ sinv) {
    const int t = blockIdx.x;
    const float* ct = cosv + t * RD;
    const float* st = sinv + t * RD;
    float* qt = q + (size_t)t * HHD;
    unsigned* qb = (unsigned*)qt;
    // roped pairs: 64 heads x 32 pairs = 2048
#pragma unroll
    for (int it = 0; it < 8; it++) {
        int p = it * 256 + threadIdx.x;
        int h = p >> 5;
        int i = p & 31;
        float c = ct[2 * i];
        float s = st[2 * i];
        int idx = h * HD + 2 * i;
        float2 v = *(float2*)(qt + idx);
        qb[idx]     = f2tf(v.x * c - v.y * s);
        qb[idx + 1] = f2tf(v.y * c + v.x * s);
    }
    // nope part: 64 heads x 64 dims = 4096 elems as 2048 float2
#pragma unroll
    for (int it = 0; it < 8; it++) {
        int p = it * 256 + threadIdx.x;
        int h = p >> 5;
        int i = p & 31;
        int idx = h * HD + RD + 2 * i;
        float2 v = *(float2*)(qt + idx);
        qb[idx]     = f2tf(v.x);
        qb[idx + 1] = f2tf(v.y);
    }
}

// ---------------------------------------------------------------------------
// LayerNorm(kp)*gamma+beta, RoPE on first RD dims, output tf32 bits -> g_ktf
// ---------------------------------------------------------------------------
__global__ __launch_bounds__(128) void ln_rope_k(const float* __restrict__ kw,
                                                 const float* __restrict__ cosv,
                                                 const float* __restrict__ sinv,
                                                 const float* __restrict__ gamma,
                                                 const float* __restrict__ beta,
                                                 unsigned* __restrict__ kout) {
    const int t = blockIdx.x;
    const int d = threadIdx.x;
    float v = kw[(size_t)t * 256 + d];
    float s1 = v, s2 = v * v;
#pragma unroll
    for (int off = 16; off; off >>= 1) {
        s1 += __shfl_xor_sync(0xffffffffu, s1, off);
        s2 += __shfl_xor_sync(0xffffffffu, s2, off);
    }
    __shared__ float r1[4], r2[4];
    if ((d & 31) == 0) { r1[d >> 5] = s1; r2[d >> 5] = s2; }
    __syncthreads();
    float sum = r1[0] + r1[1] + r1[2] + r1[3];
    float sq  = r2[0] + r2[1] + r2[2] + r2[3];
    float mu  = sum * (1.f / HD);
    float var = sq * (1.f / HD) - mu * mu;
    float kn  = (v - mu) * rsqrtf(var + EPSV) * gamma[d] + beta[d];

    __shared__ float ks[HD];
    ks[d] = kn;
    __syncthreads();
    float out = kn;
    if (d < RD) {
        float c = cosv[t * RD + (d & ~1)];
        float s = sinv[t * RD + (d & ~1)];
        float partner = ks[d ^ 1];
        out = ((d & 1) == 0) ? (kn * c - partner * s)
                             : (kn * c + partner * s);
    }
    kout[t * HD + d] = f2tf(out);
}

// ---------------------------------------------------------------------------
// scores[b,i,k] = scale * sum_h w[b,i,h] * relu( q[b,i,h,:] . k[b,k,:] )
// Double-buffered cp.async; Q and K both pre-converted tf32 bits. 2 CTAs/SM.
// ---------------------------------------------------------------------------
__global__ __launch_bounds__(256, 2) void scores_tc(const unsigned* __restrict__ q,
                                                    const unsigned* __restrict__ ktf,
                                                    const float* __restrict__ kw,
                                                    float* __restrict__ out) {
    extern __shared__ char smem[];
    const uint32_t sb = smem_u32(smem);
    const int tid = threadIdx.x;
    const int lane = tid & 31, wid = tid >> 5;
    const int warp_m = wid >> 2, warp_n = wid & 3;
    const int g = lane >> 2, qd = lane & 3;

    const int t0 = blockIdx.y * 2;
    const int b  = t0 >> 10;
    const int k0 = blockIdx.x * 128;

    const float* wrow = kw + (size_t)(t0 + warp_m) * 256 + 128;
    float w0[4], w1[4];
#pragma unroll
    for (int mt = 0; mt < 4; mt++) {
        w0[mt] = wrow[mt * 16 + g] * SCALEV;
        w1[mt] = wrow[mt * 16 + g + 8] * SCALEV;
    }

    const unsigned* qbase = q + (size_t)t0 * HHD;
    const unsigned* kbase = ktf + (size_t)(b * SQ + k0) * HD;

    auto load_stage = [&](int c, int s) {
        const int d0 = c * 32;
        const uint32_t base = sb + s * STAGE_BYTES;
#pragma unroll
        for (int r = 0; r < 4; r++) {
            int lin = r * 256 + tid;
            int row = lin >> 3, c4 = lin & 7;
            CP_ASYNC16(base + row * 144 + c4 * 16,
                       qbase + (size_t)(row >> 6) * HHD + (row & 63) * HD + d0 + c4 * 4);
        }
#pragma unroll
        for (int r = 0; r < 4; r++) {
            int lin = r * 256 + tid;
            int row = lin >> 3, c4 = lin & 7;
            CP_ASYNC16(base + TS_B_OFF + row * 144 + c4 * 16,
                       kbase + (size_t)row * HD + d0 + c4 * 4);
        }
        CP_COMMIT();
    };

    float acc[4][4][4];
#pragma unroll
    for (int i = 0; i < 4; i++)
#pragma unroll
        for (int j = 0; j < 4; j++)
#pragma unroll
            for (int r = 0; r < 4; r++) acc[i][j][r] = 0.f;

    load_stage(0, 0);

#pragma unroll
    for (int i = 0; i < 4; i++) {
        const int s = i & 1;
        if (i + 1 < 4) { load_stage(i + 1, s ^ 1); CP_WAIT(1); }
        else           { CP_WAIT(0); }
        __syncthreads();

        const unsigned* Qs = (const unsigned*)(smem + s * STAGE_BYTES);
        const unsigned* Ks = (const unsigned*)(smem + s * STAGE_BYTES + TS_B_OFF);
#pragma unroll
        for (int k8 = 0; k8 < 4; k8++) {
            unsigned a[4][4], bfr[4][2];
#pragma unroll
            for (int mt = 0; mt < 4; mt++) {
                int mrow = warp_m * 64 + mt * 16 + g;
                a[mt][0] = Qs[mrow * RST + k8 * 8 + qd];
                a[mt][1] = Qs[(mrow + 8) * RST + k8 * 8 + qd];
                a[mt][2] = Qs[mrow * RST + k8 * 8 + qd + 4];
                a[mt][3] = Qs[(mrow + 8) * RST + k8 * 8 + qd + 4];
            }
#pragma unroll
            for (int nt = 0; nt < 4; nt++) {
                int ncol = warp_n * 32 + nt * 8 + g;
                bfr[nt][0] = Ks[ncol * RST + k8 * 8 + qd];
                bfr[nt][1] = Ks[ncol * RST + k8 * 8 + qd + 4];
            }
#pragma unroll
            for (int mt = 0; mt < 4; mt++)
#pragma unroll
                for (int nt = 0; nt < 4; nt++) mma_tf32(acc[mt][nt], a[mt], bfr[nt]);
        }
        __syncthreads();
    }

    // weighted relu + head reduction (intra-warp shfl)
    float p[4][2];
#pragma unroll
    for (int nt = 0; nt < 4; nt++) { p[nt][0] = 0.f; p[nt][1] = 0.f; }
#pragma unroll
    for (int mt = 0; mt < 4; mt++) {
#pragma unroll
        for (int nt = 0; nt < 4; nt++) {
            p[nt][0] += w0[mt] * fmaxf(acc[mt][nt][0], 0.f)
                      + w1[mt] * fmaxf(acc[mt][nt][2], 0.f);
            p[nt][1] += w0[mt] * fmaxf(acc[mt][nt][1], 0.f)
                      + w1[mt] * fmaxf(acc[mt][nt][3], 0.f);
        }
    }
#pragma unroll
    for (int nt = 0; nt < 4; nt++) {
#pragma unroll
        for (int off = 4; off <= 16; off <<= 1) {
            p[nt][0] += __shfl_xor_sync(0xffffffffu, p[nt][0], off);
            p[nt][1] += __shfl_xor_sync(0xffffffffu, p[nt][1], off);
        }
    }

    if (lane < 4) {
        float* o = out + (size_t)(t0 + warp_m) * SQ + k0 + warp_n * 32;
#pragma unroll
        for (int nt = 0; nt < 4; nt++)
            *(float2*)(o + nt * 8 + lane * 2) = make_float2(p[nt][0], p[nt][1]);
    }
}

// ---------------------------------------------------------------------------
// launch
// ---------------------------------------------------------------------------
extern "C" void kernel_launch(void* const* d_in, const int* in_sizes, int n_in,
                              void* d_out, int out_size) {
    const float* x    = (const float*)d_in[0];   // [2048, 7168]
    const float* qr   = (const float*)d_in[1];   // [2048, 1536]
    const float* cosv = (const float*)d_in[2];   // [2048, 64]
    const float* sinv = (const float*)d_in[3];   // [2048, 64]
    const float* wqb  = (const float*)d_in[4];   // [1536, 8192]
    const float* wk   = (const float*)d_in[5];   // [7168, 128]
    const float* wpr  = (const float*)d_in[6];   // [7168, 64]
    const float* gam  = (const float*)d_in[7];   // [128]
    const float* bet  = (const float*)d_in[8];   // [128]
    float* out = (float*)d_out;

    float *q, *kwp, *kwb;
    unsigned *qrt, *xt, *wqt, *bkw, *ktf;
    cudaGetSymbolAddress((void**)&q,   g_q);
    cudaGetSymbolAddress((void**)&qrt, g_qrt);
    cudaGetSymbolAddress((void**)&xt,  g_xt);
    cudaGetSymbolAddress((void**)&wqt, g_wqt);
    cudaGetSymbolAddress((void**)&bkw, g_bkw);
    cudaGetSymbolAddress((void**)&kwp, g_kwp);
    cudaGetSymbolAddress((void**)&kwb, g_kw);
    cudaGetSymbolAddress((void**)&ktf, g_ktf);

    static bool attr_set = false;
    if (!attr_set) {
        cudaFuncSetAttribute(tc_mma_gemm, cudaFuncAttributeMaxDynamicSharedMemorySize, SMEM_PIPE);
        cudaFuncSetAttribute(scores_tc,  cudaFuncAttributeMaxDynamicSharedMemorySize, SMEM_PIPE);
        attr_set = true;
    }

    // operand prep: tf32 bit conversions (A-side elementwise, B-side transposed)
    cvt_tf<<<(TT * QL / 4) / 256, 256>>>(qr, qrt);
    cvt_tf<<<(TT * DIM / 4) / 256, 256>>>(x, xt);
    transpose_tf<<<dim3(HHD / 32, QL / 32), dim3(32, 8)>>>(wqb, wqt);
    pack_kw<<<dim3(8, DIM / 32), dim3(32, 8)>>>(wk, wpr, bkw);

    // q = qr @ Wq   [2048 x 8192 x 1536]
    tc_mma_gemm<<<dim3(HHD / 128, TT / 128, 1), 256, SMEM_PIPE>>>(qrt, wqt, q, QL, HHD, QL / 32);
    // kp|w = x @ (Wk||Wproj)  split-K=8 partials, then reduce
    tc_mma_gemm<<<dim3(2, TT / 128, KSPL), 256, SMEM_PIPE>>>(xt, bkw, kwp, DIM, 256, DIM / 32 / KSPL);
    reduce_kw<<<(TT * 256 / 4) / 256, 256>>>(kwp, kwb);

    // rope q in place (also converts q to tf32 bits)
    rope_q<<<TT, 256>>>(q, cosv, sinv);
    // layernorm + rope k -> tf32 bits
    ln_rope_k<<<TT, 128>>>(kwb, cosv, sinv, gam, bet, ktf);
    // scores
    scores_tc<<<dim3(SQ / 128, TT / 2), 256, SMEM_PIPE>>>((const unsigned*)q, ktf, kwb, out);
}